// round 14
// baseline (speedup 1.0000x reference)
#include <cuda_runtime.h>

#define NH 1024
#define NB 64
#define TT 512
#define THH 256
#define NCTA 128

// output layout (floats): hys[B,T,H] | hzs[B,T,H] | us[B,256,H] | spikes[B,256,H]
#define HZS_OFF 33554432ull
#define US_OFF  67108864ull
#define SP_OFF  83886080ull

typedef unsigned long long ull;

// ---------------- device scratch (static globals: allocation-free) ---------
__device__ float g_hy[2][NH][NB];              // ping-pong hy, transposed [k][b]
__device__ float g_hz[NH][NB];                 // final hz, transposed
__device__ float g_xw[(size_t)THH * NB * NH];  // x_t @ x2h, [t][b][n]
__device__ float g_hyW[NB * NH];               // hy_final @ h2h, [b][n]
__device__ unsigned g_bar2[64];                // [0] and [32]: per-half counters

__device__ __forceinline__ ull fma2(ull a, ull b, ull c) {
    ull d; asm("fma.rn.f32x2 %0, %1, %2, %3;" : "=l"(d) : "l"(a), "l"(b), "l"(c));
    return d;
}
__device__ __forceinline__ ull add2(ull a, ull b) {
    ull d; asm("add.rn.f32x2 %0, %1, %2;" : "=l"(d) : "l"(a), "l"(b));
    return d;
}
__device__ __forceinline__ ull pack2(float x) {
    ull r; asm("mov.b64 %0, {%1, %1};" : "=l"(r) : "f"(x)); return r;
}
__device__ __forceinline__ void unpack2(ull v, float& lo, float& hi) {
    asm("mov.b64 {%0, %1}, %2;" : "=f"(lo), "=f"(hi) : "l"(v));
}
__device__ __forceinline__ void bar_arrive(unsigned* p) {
    asm volatile("red.release.gpu.global.add.u32 [%0], 1;" :: "l"(p) : "memory");
}
__device__ __forceinline__ unsigned bar_peek(unsigned* p) {
    unsigned v;
    asm volatile("ld.acquire.gpu.global.u32 %0, [%1];" : "=r"(v) : "l"(p) : "memory");
    return v;
}

// --------------------------------- init ------------------------------------
__global__ void init_kernel() {
    int i = blockIdx.x * blockDim.x + threadIdx.x;
    if (i < NH * NB) ((float*)g_hy)[i] = 0.0f;  // buffer 0 only (step 0 reads it)
    if (i < 64) g_bar2[i] = 0u;
}

// --------------- xw[t][b][n] = sum_i x[b][t][i] * x2h[i][n] ----------------
__global__ void xw_kernel(const float* __restrict__ x,
                          const float* __restrict__ x2h) {
    __shared__ float xS[64][64];
    const int t = blockIdx.y, n0 = blockIdx.x * 128, tid = threadIdx.x;
    {
        int b = tid >> 2, part = tid & 3;
        const float4* src = (const float4*)(x + ((size_t)b * TT + t) * 64 + part * 16);
        float4* dst = (float4*)&xS[b][part * 16];
        dst[0] = src[0]; dst[1] = src[1]; dst[2] = src[2]; dst[3] = src[3];
    }
    __syncthreads();
    const int n = n0 + (tid & 127);
    const int b0 = (tid >> 7) * 32;
    float acc[32];
#pragma unroll
    for (int bb = 0; bb < 32; ++bb) acc[bb] = 0.0f;
    for (int i = 0; i < 64; ++i) {
        float w = __ldg(&x2h[(size_t)i * NH + n]);
#pragma unroll
        for (int bb = 0; bb < 32; ++bb) acc[bb] = fmaf(xS[b0 + bb][i], w, acc[bb]);
    }
#pragma unroll
    for (int bb = 0; bb < 32; ++bb)
        g_xw[((size_t)t * NB + b0 + bb) * NH + n] = acc[bb];
}

// ----------------- persistent harmonic kernel (256 steps + hyW) ------------
// 128 CTAs = 64 col-blocks x 2 batch-halves (independent barrier per half).
// CTA owns 16 cols x 32 batches, K = 1024.
// GEMM role: thread tile = 4 b x 8 cols x 64 k (16 f32x2 accumulators).
//   bq = tid&7 (b-quad), cg = (tid>>3)&1 (col half), kp = tid>>4 (k-split 16).
// Update role: uj2 = tid&7 (col-PAIR), ub = tid>>3 (batch) -> thread owns
//   cols (n0+2uj2, n0+2uj2+1) for batch b0+ub, register-resident all steps.
__global__ void __launch_bounds__(256, 1) harm_kernel(
    const float* __restrict__ W, const float* __restrict__ bias,
    const float* __restrict__ gam, const float* __restrict__ eps,
    float* __restrict__ out) {
    extern __shared__ float sm[];
    float* Wb = sm;                          // [1024][16]          64 KB
    ull*   P2 = (ull*)(sm + NH * 16);        // [16*8][33] f32x2    33 KB

    const int tid = threadIdx.x;
    const int n0 = (blockIdx.x >> 1) * 16, b0 = (blockIdx.x & 1) * 32;
    unsigned* barp = &g_bar2[(blockIdx.x & 1) * 32];

    // load W slice ONCE for the whole run
    for (int k = tid; k < NH; k += 256) {
        const float4* src = (const float4*)(W + (size_t)k * NH + n0);
        float4* dst = (float4*)(Wb + k * 16);
        dst[0] = src[0]; dst[1] = src[1]; dst[2] = src[2]; dst[3] = src[3];
    }

    // update-role constants/state (2 adjacent cols, 1 batch)
    const int uj2 = tid & 7, ub = tid >> 3;
    const int n_u = n0 + 2 * uj2;
    const int b_u = b0 + ub;
    const float bi0 = bias[n_u], bi1 = bias[n_u + 1];
    const float ga0 = gam[n_u],  ga1 = gam[n_u + 1];
    const float ep0 = eps[n_u],  ep1 = eps[n_u + 1];
    float hy0 = 0.0f, hz0 = 0.0f, hy1 = 0.0f, hz1 = 0.0f;

    // GEMM-role constants
    const int bq = tid & 7;              // b-quad: local b = bq*4 .. +3
    const int cg = (tid >> 3) & 1;       // col half
    const int kp = tid >> 4;             // 0..15
    const int c0 = cg * 8;
    const int k0 = kp * 64;
    const int bb = b0 + bq * 4;          // global batch base (16B-aligned)

    // prefetch xw for step 0
    float2 xwv = *(const float2*)&g_xw[(size_t)b_u * NH + n_u];
    __syncthreads();

    for (int s = 0; s <= THH; ++s) {
        const int cur = s & 1;
        const float* hyk = &g_hy[cur][0][0] + (size_t)k0 * NB + bb;

        // ---- GEMM: 4 b x 8 cols x 64 k, 2-deep group prefetch ----
        ull acc[16];
#pragma unroll
        for (int p = 0; p < 16; ++p) acc[p] = 0ull;

        float4 hA[4], hB[4];
#pragma unroll
        for (int q = 0; q < 4; ++q) {
            hA[q] = __ldcg((const float4*)(hyk + (size_t)q * NB));
            hB[q] = __ldcg((const float4*)(hyk + (size_t)(4 + q) * NB));
        }

        for (int kb = 0; kb < 64; kb += 4) {
            float4 hc[4];
#pragma unroll
            for (int q = 0; q < 4; ++q) hc[q] = hA[q];
#pragma unroll
            for (int q = 0; q < 4; ++q) hA[q] = hB[q];
            if (kb + 8 < 64) {
#pragma unroll
                for (int q = 0; q < 4; ++q)
                    hB[q] = __ldcg((const float4*)(hyk + (size_t)(kb + 8 + q) * NB));
            }
#pragma unroll
            for (int q = 0; q < 4; ++q) {
                const float* wrow = Wb + (k0 + kb + q) * 16 + c0;
                ulonglong2 wA = *(const ulonglong2*)(wrow);
                ulonglong2 wB = *(const ulonglong2*)(wrow + 4);
                ull hh;
                hh = pack2(hc[q].x);
                acc[0]  = fma2(hh, wA.x, acc[0]);  acc[1]  = fma2(hh, wA.y, acc[1]);
                acc[2]  = fma2(hh, wB.x, acc[2]);  acc[3]  = fma2(hh, wB.y, acc[3]);
                hh = pack2(hc[q].y);
                acc[4]  = fma2(hh, wA.x, acc[4]);  acc[5]  = fma2(hh, wA.y, acc[5]);
                acc[6]  = fma2(hh, wB.x, acc[6]);  acc[7]  = fma2(hh, wB.y, acc[7]);
                hh = pack2(hc[q].z);
                acc[8]  = fma2(hh, wA.x, acc[8]);  acc[9]  = fma2(hh, wA.y, acc[9]);
                acc[10] = fma2(hh, wB.x, acc[10]); acc[11] = fma2(hh, wB.y, acc[11]);
                hh = pack2(hc[q].w);
                acc[12] = fma2(hh, wA.x, acc[12]); acc[13] = fma2(hh, wA.y, acc[13]);
                acc[14] = fma2(hh, wB.x, acc[14]); acc[15] = fma2(hh, wB.y, acc[15]);
            }
        }

        // partials -> SMEM as raw f32x2: P2[(kp*8 + colpair)*33 + local_b]
        {
#pragma unroll
            for (int bi2 = 0; bi2 < 4; ++bi2) {
#pragma unroll
                for (int cp = 0; cp < 4; ++cp)
                    P2[(kp * 8 + cg * 4 + cp) * 33 + bq * 4 + bi2] = acc[bi2 * 4 + cp];
            }
        }
        __syncthreads();

        // ---- reduce over 16 K-splits in f32x2 ----
        ull sv2 = 0ull;
#pragma unroll
        for (int q = 0; q < 16; ++q)
            sv2 = add2(sv2, P2[(q * 8 + uj2) * 33 + ub]);
        float s0, s1; unpack2(sv2, s0, s1);

        if (s < THH) {
            // ---- fused update (2 cols x 1 batch per thread) ----
            float t0 = tanhf(s0 + xwv.x + bi0);
            hz0 = hz0 + 0.042f * (t0 - ga0 * hy0 - ep0 * hz0);
            hy0 = hy0 + 0.042f * hz0;
            float t1 = tanhf(s1 + xwv.y + bi1);
            hz1 = hz1 + 0.042f * (t1 - ga1 * hy1 - ep1 * hz1);
            hy1 = hy1 + 0.042f * hz1;

            g_hy[cur ^ 1][n_u][b_u]     = hy0;
            g_hy[cur ^ 1][n_u + 1][b_u] = hy1;
            if (s == THH - 1) {
                g_hz[n_u][b_u]     = hz0;
                g_hz[n_u + 1][b_u] = hz1;
            }
            __syncthreads();                    // all hy writes issued
            if (tid == 0) bar_arrive(barp);     // release: orders CTA's hy writes

            // overlap with barrier wait: trajectory stores + next xw prefetch
            size_t o = ((size_t)b_u * TT + s) * NH + n_u;
            *(float2*)(out + o)           = make_float2(hy0, hy1);
            *(float2*)(out + HZS_OFF + o) = make_float2(hz0, hz1);
            if (s + 1 < THH)
                xwv = *(const float2*)&g_xw[((size_t)(s + 1) * NB + b_u) * NH + n_u];

            if (tid == 0) {
                const unsigned tgt = 64u * (unsigned)(s + 1);
                while (bar_peek(barp) < tgt) { }
            }
            __syncthreads();
        } else {
            // s == 256: hyW = hy_final @ h2h
            *(float2*)&g_hyW[(size_t)b_u * NH + n_u] = make_float2(s0, s1);
        }
    }
}

// ------------------------- spiking (LIF) phase -----------------------------
// serial chain per (b,n); xw loads are u-independent -> batch-prefetch 8.
__global__ void spike_kernel(float* __restrict__ out) {
    const int idx = blockIdx.x * 256 + threadIdx.x;   // 65536 threads
    const int b = idx >> 10, n = idx & 1023;
    const float hw = g_hyW[idx];
    const float* xp = g_xw + (size_t)b * NH + n;
    float* us = out + US_OFF + (size_t)b * THH * NH + n;
    float* sp = out + SP_OFF + (size_t)b * THH * NH + n;
    float u = 0.0f;
    for (int tb = 0; tb < THH; tb += 8) {
        float xv[8];
#pragma unroll
        for (int i = 0; i < 8; ++i)
            xv[i] = __ldg(xp + (size_t)(tb + i) * (NB * NH));
#pragma unroll
        for (int i = 0; i < 8; ++i) {
            const int t = tb + i;
            float spike = (u > 0.008f) ? 1.0f : 0.0f;
            u = (u > 0.008f) ? 0.001f : u;
            u = u + (-u + hw + xv[i]) * 0.00105f;
            __stcs(us + (size_t)t * NH, u);
            __stcs(sp + (size_t)t * NH, spike);
        }
    }
}

// ----------- broadcast hy/hz into trajectory for t in [256, 512) -----------
// 262144 threads; each writes 16 timesteps of one float4.
__global__ void fill_kernel(float* __restrict__ out) {
    const int idx = blockIdx.x * 256 + threadIdx.x;
    const int n4 = (idx & 255) * 4;
    const int b = (idx >> 8) & 63;
    const int tc = idx >> 14;                 // 0..15
    float4 hy = make_float4(g_hy[0][n4][b], g_hy[0][n4 + 1][b],
                            g_hy[0][n4 + 2][b], g_hy[0][n4 + 3][b]);
    float4 hz = make_float4(g_hz[n4][b], g_hz[n4 + 1][b],
                            g_hz[n4 + 2][b], g_hz[n4 + 3][b]);
    const int t0 = THH + tc * 16;
    float* hys = out + ((size_t)b * TT + t0) * NH + n4;
    float* hzs = out + HZS_OFF + ((size_t)b * TT + t0) * NH + n4;
#pragma unroll
    for (int t = 0; t < 16; ++t) {
        __stcs((float4*)(hys + (size_t)t * NH), hy);
        __stcs((float4*)(hzs + (size_t)t * NH), hz);
    }
}

// ---------------------------------------------------------------------------
extern "C" void kernel_launch(void* const* d_in, const int* in_sizes, int n_in,
                              void* d_out, int out_size) {
    const float* x    = (const float*)d_in[0];
    const float* x2h  = (const float*)d_in[1];
    const float* h2h  = (const float*)d_in[2];
    const float* bias = (const float*)d_in[3];
    const float* gam  = (const float*)d_in[4];
    const float* eps  = (const float*)d_in[5];
    float* out = (float*)d_out;

    const int smem = NH * 16 * 4 + 16 * 8 * 33 * 8;   // 99328 B
    static int attr_done = 0;
    if (!attr_done) {
        cudaFuncSetAttribute(harm_kernel,
                             cudaFuncAttributeMaxDynamicSharedMemorySize, smem);
        attr_done = 1;
    }

    init_kernel<<<256, 256>>>();
    xw_kernel<<<dim3(8, 256), 256>>>(x, x2h);
    harm_kernel<<<NCTA, 256, smem>>>(h2h, bias, gam, eps, out);
    spike_kernel<<<256, 256>>>(out);
    fill_kernel<<<1024, 256>>>(out);
}